// round 10
// baseline (speedup 1.0000x reference)
#include <cuda_runtime.h>

// Fixed problem shape (GNNReachabilityNet): N=100000 nodes, E=1600000 edges, G=64 graphs.
#define NMAX  100352
#define GMAX  64
#define EMAXH 800000   // max edge pairs (E/2)

struct Params {
    float p1[11], q1[11], p2[11], q2[11];
    float ps, qs, s0, b2, bo;
};

__device__ Params   gP;
__device__ float    g_alpha[NMAX];   // alpha = x.p2
__device__ float2   g_ub[NMAX];      // (beta+gamma+ps, beta+s0)  -- w precursors
__device__ float    g_delta[NMAX];   // delta = x.q1
__device__ float2   g_agg[NMAX];     // (sum alpha over incoming, deg)
__device__ float    g_aggs[NMAX];    // sum of w[src] over incoming
__device__ int4     g_eidx[EMAXH];   // packed (s0,d0,s1,d1) per edge pair
__device__ unsigned g_outmax[GMAX];  // order-encoded float max
__device__ unsigned g_done = 0;
__device__ int      g_flag;          // 1 = int64 indices, 0 = int32

__device__ __forceinline__ unsigned enc_f(float f) {
    unsigned u = __float_as_uint(f);
    return (u & 0x80000000u) ? ~u : (u | 0x80000000u);
}
__device__ __forceinline__ float dec_f(unsigned e) {
    return (e & 0x80000000u) ? __uint_as_float(e ^ 0x80000000u) : __uint_as_float(~e);
}
#define ENC_NEG_INF 0x007FFFFFu

// ---------------------------------------------------------------------------
// K1: weight fold, coalesced loops (proven R3/R9 pattern), fp32.
// Also: dtype detect, init g_outmax / g_done.
// ---------------------------------------------------------------------------
__global__ void k_fold(const float* __restrict__ Wv,  const float* __restrict__ bv,
                       const float* __restrict__ We1, const float* __restrict__ be1,
                       const float* __restrict__ Wx,  const float* __restrict__ bx,
                       const float* __restrict__ We2, const float* __restrict__ be2,
                       const float* __restrict__ Wo,  const float* __restrict__ bo,
                       const unsigned* __restrict__ ei_words) {
    __shared__ float M1[11 * 128], M2[11 * 128];
    __shared__ float A1[11 * 64],  A2[11 * 64];
    __shared__ float c1[128], c2[64], wev[64], wfv[64];
    const int t = threadIdx.x;  // 256 threads

    if (t == 0) {
        // int64 little-endian nonneg < 2^31 => odd 32-bit words all zero.
        int nz = 0;
#pragma unroll
        for (int i = 0; i < 64; i++) nz += (ei_words[2 * i + 1] != 0u);
        g_flag = (nz == 0);
        g_done = 0u;
    }
    if (t < GMAX) g_outmax[t] = ENC_NEG_INF;

    // M1 = Wv@Wa + Pc, M2 = Wv@Wb + Pd  (coalesced over m)
    for (int idx = t; idx < 11 * 128; idx += 256) {
        int i = idx / 128, m = idx % 128;
        float a1 = 0.f, a2 = 0.f;
        for (int k = 0; k < 64; k++) {
            float wk = Wv[i * 64 + k];
            a1 += wk * We1[k * 128 + m];
            a2 += wk * We1[(64 + k) * 128 + m];
        }
        if (i == 9)  { a1 += We1[128 * 128 + m]; a2 += We1[130 * 128 + m]; }
        if (i == 10) { a1 += We1[129 * 128 + m]; a2 += We1[131 * 128 + m]; }
        M1[idx] = a1; M2[idx] = a2;
    }
    for (int m = t; m < 128; m += 256) {
        float c = be1[m];
        for (int k = 0; k < 64; k++)
            c += bv[k] * (We1[k * 128 + m] + We1[(64 + k) * 128 + m]);
        c1[m] = c;
    }
    for (int j = t; j < 64; j += 256) {
        float a = 0.f, b = 0.f;
        for (int o = 0; o < 64; o++) {
            a += We2[j * 64 + o]        * Wo[o];
            b += We2[(64 + j) * 64 + o] * Wo[o];
        }
        wev[j] = a; wfv[j] = b;
    }
    __syncthreads();
    // A1 = M1@Wx, A2 = M2@Wx  (coalesced over o)
    for (int idx = t; idx < 11 * 64; idx += 256) {
        int i = idx / 64, o = idx % 64;
        float a1 = 0.f, a2 = 0.f;
        for (int m = 0; m < 128; m++) {
            float wx = Wx[m * 64 + o];
            a1 += M1[i * 128 + m] * wx;
            a2 += M2[i * 128 + m] * wx;
        }
        A1[idx] = a1; A2[idx] = a2;
    }
    for (int o = t; o < 64; o += 256) {
        float c = bx[o];
        for (int m = 0; m < 128; m++) c += c1[m] * Wx[m * 64 + o];
        c2[o] = c;
    }
    __syncthreads();
    if (t < 11) {
        int i = t;
        float a = 0.f, b = 0.f, g = 0.f, d = 0.f;
        for (int o = 0; o < 64; o++) {
            a += A2[i * 64 + o] * wfv[o]; // p2 -> alpha
            b += A2[i * 64 + o] * wev[o]; // q2 -> beta
            g += A1[i * 64 + o] * wfv[o]; // p1 -> gamma
            d += A1[i * 64 + o] * wev[o]; // q1 -> delta
        }
        gP.p2[i] = a; gP.q2[i] = b;
        gP.p1[i] = g; gP.q1[i] = d;
    }
    if (t == 32) {
        float ps = 0.f, qs = 0.f, s0 = 0.f, b2 = 0.f;
        for (int o = 0; o < 64; o++) {
            ps += c2[o] * wfv[o];
            qs += c2[o] * wev[o];
            s0 += bx[o] * wfv[o];
            b2 += be2[o] * Wo[o];
        }
        gP.ps = ps; gP.qs = qs; gP.s0 = s0;
        gP.b2 = b2 + bo[0]; gP.bo = bo[0];
    }
}

// ---------------------------------------------------------------------------
// K2: per-node 11-dim dots (x staged via smem float4); zero accumulators.
// Writes w-precursors: g_ub = (beta+gamma+ps, beta+s0).
// ---------------------------------------------------------------------------
__global__ void __launch_bounds__(256) k_dots(const float* __restrict__ x, int n) {
    __shared__ float sx[256 * 11];
    __shared__ float sp1[11], sq1[11], sp2[11], sq2[11];
    __shared__ float s_ps, s_s0;
    int t = threadIdx.x;
    if (t < 11) {
        sp1[t] = gP.p1[t]; sq1[t] = gP.q1[t];
        sp2[t] = gP.p2[t]; sq2[t] = gP.q2[t];
    }
    if (t == 11) { s_ps = gP.ps; s_s0 = gP.s0; }
    int base = blockIdx.x * 2816;
    int lim = n * 11 - base;
    if (lim >= 2816) {
        const float4* xv = (const float4*)(x + base);
        float4* s4 = (float4*)sx;
        s4[t]       = xv[t];
        s4[t + 256] = xv[t + 256];
        if (t + 512 < 704) s4[t + 512] = xv[t + 512];
    } else {
        for (int j = t; j < 2816; j += 256)
            sx[j] = (j < lim) ? x[base + j] : 0.f;
    }
    __syncthreads();
    int v = blockIdx.x * 256 + t;
    if (v < n) {
        float a = 0.f, b = 0.f, g = 0.f, d = 0.f;
#pragma unroll
        for (int i = 0; i < 11; i++) {
            float xv = sx[t * 11 + i];
            a += xv * sp2[i]; b += xv * sq2[i];
            g += xv * sp1[i]; d += xv * sq1[i];
        }
        g_alpha[v] = a;
        g_ub[v]    = make_float2(b + g + s_ps, b + s_s0);
        g_delta[v] = d;
        g_agg[v]   = make_float2(0.f, 0.f);
        g_aggs[v]  = 0.f;
    }
}

// ---------------------------------------------------------------------------
// K3: edge pass 1 — 2 edges/thread: wide index loads, write packed int32
// pairs for pass 2, gather alpha (4B), float2 RED (sum_alpha, deg).
// ---------------------------------------------------------------------------
__global__ void __launch_bounds__(256) k_edge1(const void* __restrict__ ei, int E) {
    int i = blockIdx.x * 256 + threadIdx.x;
    int e0 = 2 * i;
    if (e0 >= E) return;
    const bool f64 = (g_flag != 0);
    int s0, s1, d0, d1;
    bool two = (e0 + 1 < E);
    if (f64) {
        const long long* p = (const long long*)ei;
        if (two) {
            longlong2 sv = *(const longlong2*)(p + e0);
            s0 = (int)sv.x; s1 = (int)sv.y;
            if ((E & 1) == 0) {
                longlong2 dv = *(const longlong2*)(p + E + e0);
                d0 = (int)dv.x; d1 = (int)dv.y;
            } else {
                d0 = (int)p[E + e0]; d1 = (int)p[E + e0 + 1];
            }
        } else {
            s0 = (int)p[e0]; d0 = (int)p[E + e0]; s1 = s0; d1 = -1;
        }
    } else {
        const int* p = (const int*)ei;
        if (two) {
            int2 sv = *(const int2*)(p + e0);
            s0 = sv.x; s1 = sv.y;
            if ((E & 1) == 0) {
                int2 dv = *(const int2*)(p + E + e0);
                d0 = dv.x; d1 = dv.y;
            } else {
                d0 = p[E + e0]; d1 = p[E + e0 + 1];
            }
        } else {
            s0 = p[e0]; d0 = p[E + e0]; s1 = s0; d1 = -1;
        }
    }
    g_eidx[i] = make_int4(s0, d0, s1, d1);

    float a0 = __ldg(&g_alpha[s0]);
    if (d1 >= 0) {
        float a1 = __ldg(&g_alpha[s1]);
        if (d0 == d1) {
            atomicAdd(&g_agg[d0], make_float2(a0 + a1, 2.f));
        } else {
            atomicAdd(&g_agg[d0], make_float2(a0, 1.f));
            atomicAdd(&g_agg[d1], make_float2(a1, 1.f));
        }
    } else {
        atomicAdd(&g_agg[d0], make_float2(a0, 1.f));
    }
}

// ---------------------------------------------------------------------------
// K4: edge pass 2 — 2 edges/thread from packed pairs; computes w[src]
// inline (w = deg>0 ? ub.x + sum_alpha/deg : ub.y), scalar RED on dst.
// L1 is flushed at launch boundary, so __ldg of atomic-written g_agg is
// coherent with edge pass 1's L2 state.
// ---------------------------------------------------------------------------
__global__ void __launch_bounds__(256) k_edge2(int E) {
    int i = blockIdx.x * 256 + threadIdx.x;
    if (2 * i >= E) return;
    int4 p = g_eidx[i];

    float2 ub0 = __ldg(&g_ub[p.x]);
    float2 ag0 = __ldg(&g_agg[p.x]);
    float w0 = (ag0.y > 0.f) ? (ub0.x + __fdividef(ag0.x, ag0.y)) : ub0.y;
    if (p.w >= 0) {
        float2 ub1 = __ldg(&g_ub[p.z]);
        float2 ag1 = __ldg(&g_agg[p.z]);
        float w1 = (ag1.y > 0.f) ? (ub1.x + __fdividef(ag1.x, ag1.y)) : ub1.y;
        if (p.y == p.w) {
            atomicAdd(&g_aggs[p.y], w0 + w1);
        } else {
            atomicAdd(&g_aggs[p.y], w0);
            atomicAdd(&g_aggs[p.w], w1);
        }
    } else {
        atomicAdd(&g_aggs[p.y], w0);
    }
}

// ---------------------------------------------------------------------------
// K5: node_out + segment max + last-block writeout.
// ---------------------------------------------------------------------------
__global__ void __launch_bounds__(256) k_final(const void* __restrict__ batch,
                                               float* out, int n, int out_n) {
    __shared__ unsigned smax[GMAX];
    __shared__ int s_done;
    int t = threadIdx.x;
    if (t < GMAX) smax[t] = ENC_NEG_INF;
    __syncthreads();

    const bool f64 = (g_flag != 0);
    float qb = gP.qs + gP.b2, bo_ = gP.bo;
    int v = blockIdx.x * 256 + t;
    if (v < n) {
        float deg = g_agg[v].y;
        float no = (deg > 0.f)
                 ? (g_delta[v] + qb + (1.f / deg) * g_aggs[v])
                 : bo_;
        int g = f64 ? (int)((const long long*)batch)[v]
                    : ((const int*)batch)[v];
        atomicMax(&smax[g], enc_f(no));
    }
    __syncthreads();
    if (t < GMAX && smax[t] != ENC_NEG_INF)
        atomicMax(&g_outmax[t], smax[t]);
    __syncthreads();
    if (t == 0) {
        __threadfence();
        s_done = (atomicAdd(&g_done, 1u) == gridDim.x - 1u);
    }
    __syncthreads();
    if (s_done && t < GMAX && t < out_n) {
        unsigned vmax = atomicAdd(&g_outmax[t], 0u);  // coherent L2 read
        out[t] = dec_f(vmax);
    }
}

extern "C" void kernel_launch(void* const* d_in, const int* in_sizes, int n_in,
                              void* d_out, int out_size) {
    const float* x     = (const float*)d_in[0];
    const void*  ei    = d_in[1];
    const void*  batch = d_in[2];
    const float* Wv  = (const float*)d_in[3];
    const float* bv  = (const float*)d_in[4];
    const float* We1 = (const float*)d_in[5];
    const float* be1 = (const float*)d_in[6];
    const float* Wx  = (const float*)d_in[7];
    const float* bx  = (const float*)d_in[8];
    const float* We2 = (const float*)d_in[9];
    const float* be2 = (const float*)d_in[10];
    const float* Wo  = (const float*)d_in[11];
    const float* bo  = (const float*)d_in[12];
    float* out = (float*)d_out;

    int n = in_sizes[0] / 11;   // 100000
    int E = in_sizes[1] / 2;    // 1600000
    if (n > NMAX) n = NMAX;
    if (E > 2 * EMAXH) E = 2 * EMAXH;

    const int TPB = 256;
    int nb_n = (n + TPB - 1) / TPB;
    int nb_e = ((E + 1) / 2 + TPB - 1) / TPB;

    k_fold<<<1, 256>>>(Wv, bv, We1, be1, Wx, bx, We2, be2, Wo, bo,
                       (const unsigned*)ei);
    k_dots<<<nb_n, TPB>>>(x, n);
    k_edge1<<<nb_e, TPB>>>(ei, E);
    k_edge2<<<nb_e, TPB>>>(E);
    k_final<<<nb_n, TPB>>>(batch, out, n, out_size);
}

// round 11
// speedup vs baseline: 1.0273x; 1.0273x over previous
#include <cuda_runtime.h>

// Fixed problem shape (GNNReachabilityNet): N=100000 nodes, E=1600000 edges, G=64 graphs.
#define NMAX  100352
#define GMAX  64
#define EMAXH 800000   // max edge pairs (E/2)

struct Params {
    float p1[11], q1[11], p2[11], q2[11];
    float ps, qs, s0, b2, bo;
};

__device__ Params   gP;
__device__ float    g_alpha[NMAX];   // alpha = x.p2
__device__ float2   g_bg[NMAX];      // (beta = x.q2, gamma = x.p1)
__device__ float    g_delta[NMAX];   // delta = x.q1
__device__ float2   g_agg[NMAX];     // (sum alpha over incoming, deg)
__device__ float    g_w[NMAX];       // w[u] = beta[u] + s[u]
__device__ float    g_aggs[NMAX];    // sum of w[src] over incoming
__device__ int4     g_eidx[EMAXH];   // packed (s0,d0,s1,d1) per edge pair
__device__ unsigned g_outmax[GMAX];  // order-encoded float max
__device__ unsigned g_done = 0;
__device__ int      g_flag;          // 1 = int64 indices, 0 = int32

__device__ __forceinline__ unsigned enc_f(float f) {
    unsigned u = __float_as_uint(f);
    return (u & 0x80000000u) ? ~u : (u | 0x80000000u);
}
__device__ __forceinline__ float dec_f(unsigned e) {
    return (e & 0x80000000u) ? __uint_as_float(e ^ 0x80000000u) : __uint_as_float(~e);
}
#define ENC_NEG_INF 0x007FFFFFu

// ---------------------------------------------------------------------------
// K1: weight fold, coalesced loops (proven R3/R9 pattern), fp32.
// Also: dtype detect, init g_outmax / g_done.
// ---------------------------------------------------------------------------
__global__ void k_fold(const float* __restrict__ Wv,  const float* __restrict__ bv,
                       const float* __restrict__ We1, const float* __restrict__ be1,
                       const float* __restrict__ Wx,  const float* __restrict__ bx,
                       const float* __restrict__ We2, const float* __restrict__ be2,
                       const float* __restrict__ Wo,  const float* __restrict__ bo,
                       const unsigned* __restrict__ ei_words) {
    __shared__ float M1[11 * 128], M2[11 * 128];
    __shared__ float A1[11 * 64],  A2[11 * 64];
    __shared__ float c1[128], c2[64], wev[64], wfv[64];
    const int t = threadIdx.x;  // 256 threads

    if (t == 0) {
        // int64 little-endian nonneg < 2^31 => odd 32-bit words all zero.
        int nz = 0;
#pragma unroll
        for (int i = 0; i < 64; i++) nz += (ei_words[2 * i + 1] != 0u);
        g_flag = (nz == 0);
        g_done = 0u;
    }
    if (t < GMAX) g_outmax[t] = ENC_NEG_INF;

    // M1 = Wv@Wa + Pc, M2 = Wv@Wb + Pd  (coalesced over m)
    for (int idx = t; idx < 11 * 128; idx += 256) {
        int i = idx / 128, m = idx % 128;
        float a1 = 0.f, a2 = 0.f;
        for (int k = 0; k < 64; k++) {
            float wk = Wv[i * 64 + k];
            a1 += wk * We1[k * 128 + m];
            a2 += wk * We1[(64 + k) * 128 + m];
        }
        if (i == 9)  { a1 += We1[128 * 128 + m]; a2 += We1[130 * 128 + m]; }
        if (i == 10) { a1 += We1[129 * 128 + m]; a2 += We1[131 * 128 + m]; }
        M1[idx] = a1; M2[idx] = a2;
    }
    for (int m = t; m < 128; m += 256) {
        float c = be1[m];
        for (int k = 0; k < 64; k++)
            c += bv[k] * (We1[k * 128 + m] + We1[(64 + k) * 128 + m]);
        c1[m] = c;
    }
    for (int j = t; j < 64; j += 256) {
        float a = 0.f, b = 0.f;
        for (int o = 0; o < 64; o++) {
            a += We2[j * 64 + o]        * Wo[o];
            b += We2[(64 + j) * 64 + o] * Wo[o];
        }
        wev[j] = a; wfv[j] = b;
    }
    __syncthreads();
    // A1 = M1@Wx, A2 = M2@Wx  (coalesced over o)
    for (int idx = t; idx < 11 * 64; idx += 256) {
        int i = idx / 64, o = idx % 64;
        float a1 = 0.f, a2 = 0.f;
        for (int m = 0; m < 128; m++) {
            float wx = Wx[m * 64 + o];
            a1 += M1[i * 128 + m] * wx;
            a2 += M2[i * 128 + m] * wx;
        }
        A1[idx] = a1; A2[idx] = a2;
    }
    for (int o = t; o < 64; o += 256) {
        float c = bx[o];
        for (int m = 0; m < 128; m++) c += c1[m] * Wx[m * 64 + o];
        c2[o] = c;
    }
    __syncthreads();
    if (t < 11) {
        int i = t;
        float a = 0.f, b = 0.f, g = 0.f, d = 0.f;
        for (int o = 0; o < 64; o++) {
            a += A2[i * 64 + o] * wfv[o]; // p2 -> alpha
            b += A2[i * 64 + o] * wev[o]; // q2 -> beta
            g += A1[i * 64 + o] * wfv[o]; // p1 -> gamma
            d += A1[i * 64 + o] * wev[o]; // q1 -> delta
        }
        gP.p2[i] = a; gP.q2[i] = b;
        gP.p1[i] = g; gP.q1[i] = d;
    }
    if (t == 32) {
        float ps = 0.f, qs = 0.f, s0 = 0.f, b2 = 0.f;
        for (int o = 0; o < 64; o++) {
            ps += c2[o] * wfv[o];
            qs += c2[o] * wev[o];
            s0 += bx[o] * wfv[o];
            b2 += be2[o] * Wo[o];
        }
        gP.ps = ps; gP.qs = qs; gP.s0 = s0;
        gP.b2 = b2 + bo[0]; gP.bo = bo[0];
    }
}

// ---------------------------------------------------------------------------
// K2: per-node 11-dim dots (x staged via smem float4); zero accumulators.
// ---------------------------------------------------------------------------
__global__ void __launch_bounds__(256) k_dots(const float* __restrict__ x, int n) {
    __shared__ float sx[256 * 11];
    __shared__ float sp1[11], sq1[11], sp2[11], sq2[11];
    int t = threadIdx.x;
    if (t < 11) {
        sp1[t] = gP.p1[t]; sq1[t] = gP.q1[t];
        sp2[t] = gP.p2[t]; sq2[t] = gP.q2[t];
    }
    int base = blockIdx.x * 2816;
    int lim = n * 11 - base;
    if (lim >= 2816) {
        const float4* xv = (const float4*)(x + base);
        float4* s4 = (float4*)sx;
        s4[t]       = xv[t];
        s4[t + 256] = xv[t + 256];
        if (t + 512 < 704) s4[t + 512] = xv[t + 512];
    } else {
        for (int j = t; j < 2816; j += 256)
            sx[j] = (j < lim) ? x[base + j] : 0.f;
    }
    __syncthreads();
    int v = blockIdx.x * 256 + t;
    if (v < n) {
        float a = 0.f, b = 0.f, g = 0.f, d = 0.f;
#pragma unroll
        for (int i = 0; i < 11; i++) {
            float xv = sx[t * 11 + i];
            a += xv * sp2[i]; b += xv * sq2[i];
            g += xv * sp1[i]; d += xv * sq1[i];
        }
        g_alpha[v] = a;
        g_bg[v]    = make_float2(b, g);
        g_delta[v] = d;
        g_agg[v]   = make_float2(0.f, 0.f);
        g_aggs[v]  = 0.f;
    }
}

// ---------------------------------------------------------------------------
// K3: edge pass 1 — 2 edges/thread: wide index loads, __stcg packed int32
// pairs for pass 2, __ldcg alpha gather (no L1 line alloc), float2 RED.
// ---------------------------------------------------------------------------
__global__ void __launch_bounds__(256) k_edge1(const void* __restrict__ ei, int E) {
    int i = blockIdx.x * 256 + threadIdx.x;
    int e0 = 2 * i;
    if (e0 >= E) return;
    const bool f64 = (g_flag != 0);
    int s0, s1, d0, d1;
    bool two = (e0 + 1 < E);
    if (f64) {
        const long long* p = (const long long*)ei;
        if (two) {
            longlong2 sv = *(const longlong2*)(p + e0);
            s0 = (int)sv.x; s1 = (int)sv.y;
            if ((E & 1) == 0) {
                longlong2 dv = *(const longlong2*)(p + E + e0);
                d0 = (int)dv.x; d1 = (int)dv.y;
            } else {
                d0 = (int)p[E + e0]; d1 = (int)p[E + e0 + 1];
            }
        } else {
            s0 = (int)p[e0]; d0 = (int)p[E + e0]; s1 = s0; d1 = -1;
        }
    } else {
        const int* p = (const int*)ei;
        if (two) {
            int2 sv = *(const int2*)(p + e0);
            s0 = sv.x; s1 = sv.y;
            if ((E & 1) == 0) {
                int2 dv = *(const int2*)(p + E + e0);
                d0 = dv.x; d1 = dv.y;
            } else {
                d0 = p[E + e0]; d1 = p[E + e0 + 1];
            }
        } else {
            s0 = p[e0]; d0 = p[E + e0]; s1 = s0; d1 = -1;
        }
    }
    __stcg(&g_eidx[i], make_int4(s0, d0, s1, d1));

    float a0 = __ldcg(&g_alpha[s0]);
    if (d1 >= 0) {
        float a1 = __ldcg(&g_alpha[s1]);
        if (d0 == d1) {
            atomicAdd(&g_agg[d0], make_float2(a0 + a1, 2.f));
        } else {
            atomicAdd(&g_agg[d0], make_float2(a0, 1.f));
            atomicAdd(&g_agg[d1], make_float2(a1, 1.f));
        }
    } else {
        atomicAdd(&g_agg[d0], make_float2(a0, 1.f));
    }
}

// ---------------------------------------------------------------------------
// K4: per-node w = beta + s.
// ---------------------------------------------------------------------------
__global__ void __launch_bounds__(256) k_nodes(int n) {
    int v = blockIdx.x * 256 + threadIdx.x;
    if (v >= n) return;
    float2 ag = g_agg[v];
    float2 bg = g_bg[v];
    float s = (ag.y > 0.f) ? (bg.y + (1.f / ag.y) * ag.x + gP.ps) : gP.s0;
    g_w[v] = bg.x + s;
}

// ---------------------------------------------------------------------------
// K5: edge pass 2 — 2 edges/thread from packed int32 pairs (__ldcg stream):
// __ldcg w gather, scalar RED: aggs[dst] += w[src].
// ---------------------------------------------------------------------------
__global__ void __launch_bounds__(256) k_edge2(int E) {
    int i = blockIdx.x * 256 + threadIdx.x;
    if (2 * i >= E) return;
    int4 p = __ldcg(&g_eidx[i]);
    float w0 = __ldcg(&g_w[p.x]);
    if (p.w >= 0) {
        float w1 = __ldcg(&g_w[p.z]);
        if (p.y == p.w) {
            atomicAdd(&g_aggs[p.y], w0 + w1);
        } else {
            atomicAdd(&g_aggs[p.y], w0);
            atomicAdd(&g_aggs[p.w], w1);
        }
    } else {
        atomicAdd(&g_aggs[p.y], w0);
    }
}

// ---------------------------------------------------------------------------
// K6: node_out + segment max + last-block writeout.
// ---------------------------------------------------------------------------
__global__ void __launch_bounds__(256) k_final(const void* __restrict__ batch,
                                               float* out, int n, int out_n) {
    __shared__ unsigned smax[GMAX];
    __shared__ int s_done;
    int t = threadIdx.x;
    if (t < GMAX) smax[t] = ENC_NEG_INF;
    __syncthreads();

    const bool f64 = (g_flag != 0);
    float qb = gP.qs + gP.b2, bo_ = gP.bo;
    int v = blockIdx.x * 256 + t;
    if (v < n) {
        float deg = g_agg[v].y;
        float no = (deg > 0.f)
                 ? (g_delta[v] + qb + (1.f / deg) * g_aggs[v])
                 : bo_;
        int g = f64 ? (int)((const long long*)batch)[v]
                    : ((const int*)batch)[v];
        atomicMax(&smax[g], enc_f(no));
    }
    __syncthreads();
    if (t < GMAX && smax[t] != ENC_NEG_INF)
        atomicMax(&g_outmax[t], smax[t]);
    __syncthreads();
    if (t == 0) {
        __threadfence();
        s_done = (atomicAdd(&g_done, 1u) == gridDim.x - 1u);
    }
    __syncthreads();
    if (s_done && t < GMAX && t < out_n) {
        unsigned vmax = atomicAdd(&g_outmax[t], 0u);  // coherent L2 read
        out[t] = dec_f(vmax);
    }
}

extern "C" void kernel_launch(void* const* d_in, const int* in_sizes, int n_in,
                              void* d_out, int out_size) {
    const float* x     = (const float*)d_in[0];
    const void*  ei    = d_in[1];
    const void*  batch = d_in[2];
    const float* Wv  = (const float*)d_in[3];
    const float* bv  = (const float*)d_in[4];
    const float* We1 = (const float*)d_in[5];
    const float* be1 = (const float*)d_in[6];
    const float* Wx  = (const float*)d_in[7];
    const float* bx  = (const float*)d_in[8];
    const float* We2 = (const float*)d_in[9];
    const float* be2 = (const float*)d_in[10];
    const float* Wo  = (const float*)d_in[11];
    const float* bo  = (const float*)d_in[12];
    float* out = (float*)d_out;

    int n = in_sizes[0] / 11;   // 100000
    int E = in_sizes[1] / 2;    // 1600000
    if (n > NMAX) n = NMAX;
    if (E > 2 * EMAXH) E = 2 * EMAXH;

    const int TPB = 256;
    int nb_n = (n + TPB - 1) / TPB;
    int nb_e = ((E + 1) / 2 + TPB - 1) / TPB;

    k_fold<<<1, 256>>>(Wv, bv, We1, be1, Wx, bx, We2, be2, Wo, bo,
                       (const unsigned*)ei);
    k_dots<<<nb_n, TPB>>>(x, n);
    k_edge1<<<nb_e, TPB>>>(ei, E);
    k_nodes<<<nb_n, TPB>>>(n);
    k_edge2<<<nb_e, TPB>>>(E);
    k_final<<<nb_n, TPB>>>(batch, out, n, out_size);
}

// round 12
// speedup vs baseline: 1.0576x; 1.0295x over previous
#include <cuda_runtime.h>

// Fixed problem shape (GNNReachabilityNet): N=100000 nodes, E=1600000 edges, G=64 graphs.
#define NMAX  100352
#define GMAX  64
#define EMAXH 800000   // max edge pairs (E/2)

struct Params {
    float p1[11], q1[11], p2[11], q2[11];
    float ps, qs, s0, b2, bo;
};

__device__ Params   gP;
__device__ float    g_alpha[NMAX];   // alpha = x.p2
__device__ float4   g_node[NMAX];    // (beta+gamma+ps, beta+s0, sum_alpha, deg)
__device__ float    g_delta[NMAX];   // delta = x.q1
__device__ float    g_aggs[NMAX];    // sum of w[src] over incoming
__device__ int4     g_eidx[EMAXH];   // packed (s0,d0,s1,d1) per edge pair
__device__ unsigned g_outmax[GMAX];  // order-encoded float max
__device__ unsigned g_done = 0;
__device__ int      g_flag;          // 1 = int64 indices, 0 = int32

__device__ __forceinline__ unsigned enc_f(float f) {
    unsigned u = __float_as_uint(f);
    return (u & 0x80000000u) ? ~u : (u | 0x80000000u);
}
__device__ __forceinline__ float dec_f(unsigned e) {
    return (e & 0x80000000u) ? __uint_as_float(e ^ 0x80000000u) : __uint_as_float(~e);
}
#define ENC_NEG_INF 0x007FFFFFu

// ---------------------------------------------------------------------------
// K1: weight fold, coalesced loops (proven R3/R9 pattern), fp32.
// Also: dtype detect, init g_outmax / g_done.
// ---------------------------------------------------------------------------
__global__ void k_fold(const float* __restrict__ Wv,  const float* __restrict__ bv,
                       const float* __restrict__ We1, const float* __restrict__ be1,
                       const float* __restrict__ Wx,  const float* __restrict__ bx,
                       const float* __restrict__ We2, const float* __restrict__ be2,
                       const float* __restrict__ Wo,  const float* __restrict__ bo,
                       const unsigned* __restrict__ ei_words) {
    __shared__ float M1[11 * 128], M2[11 * 128];
    __shared__ float A1[11 * 64],  A2[11 * 64];
    __shared__ float c1[128], c2[64], wev[64], wfv[64];
    const int t = threadIdx.x;  // 256 threads

    if (t == 0) {
        // int64 little-endian nonneg < 2^31 => odd 32-bit words all zero.
        int nz = 0;
#pragma unroll
        for (int i = 0; i < 64; i++) nz += (ei_words[2 * i + 1] != 0u);
        g_flag = (nz == 0);
        g_done = 0u;
    }
    if (t < GMAX) g_outmax[t] = ENC_NEG_INF;

    // M1 = Wv@Wa + Pc, M2 = Wv@Wb + Pd  (coalesced over m)
    for (int idx = t; idx < 11 * 128; idx += 256) {
        int i = idx / 128, m = idx % 128;
        float a1 = 0.f, a2 = 0.f;
        for (int k = 0; k < 64; k++) {
            float wk = Wv[i * 64 + k];
            a1 += wk * We1[k * 128 + m];
            a2 += wk * We1[(64 + k) * 128 + m];
        }
        if (i == 9)  { a1 += We1[128 * 128 + m]; a2 += We1[130 * 128 + m]; }
        if (i == 10) { a1 += We1[129 * 128 + m]; a2 += We1[131 * 128 + m]; }
        M1[idx] = a1; M2[idx] = a2;
    }
    for (int m = t; m < 128; m += 256) {
        float c = be1[m];
        for (int k = 0; k < 64; k++)
            c += bv[k] * (We1[k * 128 + m] + We1[(64 + k) * 128 + m]);
        c1[m] = c;
    }
    for (int j = t; j < 64; j += 256) {
        float a = 0.f, b = 0.f;
        for (int o = 0; o < 64; o++) {
            a += We2[j * 64 + o]        * Wo[o];
            b += We2[(64 + j) * 64 + o] * Wo[o];
        }
        wev[j] = a; wfv[j] = b;
    }
    __syncthreads();
    // A1 = M1@Wx, A2 = M2@Wx  (coalesced over o)
    for (int idx = t; idx < 11 * 64; idx += 256) {
        int i = idx / 64, o = idx % 64;
        float a1 = 0.f, a2 = 0.f;
        for (int m = 0; m < 128; m++) {
            float wx = Wx[m * 64 + o];
            a1 += M1[i * 128 + m] * wx;
            a2 += M2[i * 128 + m] * wx;
        }
        A1[idx] = a1; A2[idx] = a2;
    }
    for (int o = t; o < 64; o += 256) {
        float c = bx[o];
        for (int m = 0; m < 128; m++) c += c1[m] * Wx[m * 64 + o];
        c2[o] = c;
    }
    __syncthreads();
    if (t < 11) {
        int i = t;
        float a = 0.f, b = 0.f, g = 0.f, d = 0.f;
        for (int o = 0; o < 64; o++) {
            a += A2[i * 64 + o] * wfv[o]; // p2 -> alpha
            b += A2[i * 64 + o] * wev[o]; // q2 -> beta
            g += A1[i * 64 + o] * wfv[o]; // p1 -> gamma
            d += A1[i * 64 + o] * wev[o]; // q1 -> delta
        }
        gP.p2[i] = a; gP.q2[i] = b;
        gP.p1[i] = g; gP.q1[i] = d;
    }
    if (t == 32) {
        float ps = 0.f, qs = 0.f, s0 = 0.f, b2 = 0.f;
        for (int o = 0; o < 64; o++) {
            ps += c2[o] * wfv[o];
            qs += c2[o] * wev[o];
            s0 += bx[o] * wfv[o];
            b2 += be2[o] * Wo[o];
        }
        gP.ps = ps; gP.qs = qs; gP.s0 = s0;
        gP.b2 = b2 + bo[0]; gP.bo = bo[0];
    }
}

// ---------------------------------------------------------------------------
// K2: per-node 11-dim dots (x staged via smem float4); writes the packed
// node record (statics + zeroed accumulators) and zeroes g_aggs.
// ---------------------------------------------------------------------------
__global__ void __launch_bounds__(256) k_dots(const float* __restrict__ x, int n) {
    __shared__ float sx[256 * 11];
    __shared__ float sp1[11], sq1[11], sp2[11], sq2[11];
    __shared__ float s_ps, s_s0;
    int t = threadIdx.x;
    if (t < 11) {
        sp1[t] = gP.p1[t]; sq1[t] = gP.q1[t];
        sp2[t] = gP.p2[t]; sq2[t] = gP.q2[t];
    }
    if (t == 11) { s_ps = gP.ps; s_s0 = gP.s0; }
    int base = blockIdx.x * 2816;
    int lim = n * 11 - base;
    if (lim >= 2816) {
        const float4* xv = (const float4*)(x + base);
        float4* s4 = (float4*)sx;
        s4[t]       = xv[t];
        s4[t + 256] = xv[t + 256];
        if (t + 512 < 704) s4[t + 512] = xv[t + 512];
    } else {
        for (int j = t; j < 2816; j += 256)
            sx[j] = (j < lim) ? x[base + j] : 0.f;
    }
    __syncthreads();
    int v = blockIdx.x * 256 + t;
    if (v < n) {
        float a = 0.f, b = 0.f, g = 0.f, d = 0.f;
#pragma unroll
        for (int i = 0; i < 11; i++) {
            float xv = sx[t * 11 + i];
            a += xv * sp2[i]; b += xv * sq2[i];
            g += xv * sp1[i]; d += xv * sq1[i];
        }
        g_alpha[v] = a;
        g_node[v]  = make_float4(b + g + s_ps, b + s_s0, 0.f, 0.f);
        g_delta[v] = d;
        g_aggs[v]  = 0.f;
    }
}

// ---------------------------------------------------------------------------
// K3: edge pass 1 — 2 edges/thread: wide index loads, write packed int32
// pairs for pass 2, gather alpha (4B), float2 RED into g_node[d].zw.
// ---------------------------------------------------------------------------
__global__ void __launch_bounds__(256) k_edge1(const void* __restrict__ ei, int E) {
    int i = blockIdx.x * 256 + threadIdx.x;
    int e0 = 2 * i;
    if (e0 >= E) return;
    const bool f64 = (g_flag != 0);
    int s0, s1, d0, d1;
    bool two = (e0 + 1 < E);
    if (f64) {
        const long long* p = (const long long*)ei;
        if (two) {
            longlong2 sv = *(const longlong2*)(p + e0);
            s0 = (int)sv.x; s1 = (int)sv.y;
            if ((E & 1) == 0) {
                longlong2 dv = *(const longlong2*)(p + E + e0);
                d0 = (int)dv.x; d1 = (int)dv.y;
            } else {
                d0 = (int)p[E + e0]; d1 = (int)p[E + e0 + 1];
            }
        } else {
            s0 = (int)p[e0]; d0 = (int)p[E + e0]; s1 = s0; d1 = -1;
        }
    } else {
        const int* p = (const int*)ei;
        if (two) {
            int2 sv = *(const int2*)(p + e0);
            s0 = sv.x; s1 = sv.y;
            if ((E & 1) == 0) {
                int2 dv = *(const int2*)(p + E + e0);
                d0 = dv.x; d1 = dv.y;
            } else {
                d0 = p[E + e0]; d1 = p[E + e0 + 1];
            }
        } else {
            s0 = p[e0]; d0 = p[E + e0]; s1 = s0; d1 = -1;
        }
    }
    g_eidx[i] = make_int4(s0, d0, s1, d1);

    float2* acc0 = (float2*)((char*)&g_node[d0] + 8);   // .zw half, 8B-aligned
    float a0 = __ldg(&g_alpha[s0]);
    if (d1 >= 0) {
        float a1 = __ldg(&g_alpha[s1]);
        if (d0 == d1) {
            atomicAdd(acc0, make_float2(a0 + a1, 2.f));
        } else {
            float2* acc1 = (float2*)((char*)&g_node[d1] + 8);
            atomicAdd(acc0, make_float2(a0, 1.f));
            atomicAdd(acc1, make_float2(a1, 1.f));
        }
    } else {
        atomicAdd(acc0, make_float2(a0, 1.f));
    }
}

// ---------------------------------------------------------------------------
// K4: edge pass 2 — 2 edges/thread from packed pairs: ONE 16B gather of the
// src node record, inline w = deg>0 ? x + z/deg : y, scalar RED on dst.
// (Launch boundary flushed L1, so __ldg sees pass 1's L2 atomics.)
// ---------------------------------------------------------------------------
__global__ void __launch_bounds__(256) k_edge2(int E) {
    int i = blockIdx.x * 256 + threadIdx.x;
    if (2 * i >= E) return;
    int4 p = g_eidx[i];
    float4 n0 = __ldg(&g_node[p.x]);
    float w0 = (n0.w > 0.f) ? (n0.x + __fdividef(n0.z, n0.w)) : n0.y;
    if (p.w >= 0) {
        float4 n1 = __ldg(&g_node[p.z]);
        float w1 = (n1.w > 0.f) ? (n1.x + __fdividef(n1.z, n1.w)) : n1.y;
        if (p.y == p.w) {
            atomicAdd(&g_aggs[p.y], w0 + w1);
        } else {
            atomicAdd(&g_aggs[p.y], w0);
            atomicAdd(&g_aggs[p.w], w1);
        }
    } else {
        atomicAdd(&g_aggs[p.y], w0);
    }
}

// ---------------------------------------------------------------------------
// K5: node_out + segment max + last-block writeout.
// ---------------------------------------------------------------------------
__global__ void __launch_bounds__(256) k_final(const void* __restrict__ batch,
                                               float* out, int n, int out_n) {
    __shared__ unsigned smax[GMAX];
    __shared__ int s_done;
    int t = threadIdx.x;
    if (t < GMAX) smax[t] = ENC_NEG_INF;
    __syncthreads();

    const bool f64 = (g_flag != 0);
    float qb = gP.qs + gP.b2, bo_ = gP.bo;
    int v = blockIdx.x * 256 + t;
    if (v < n) {
        float deg = ((const float*)&g_node[v])[3];
        float no = (deg > 0.f)
                 ? (g_delta[v] + qb + (1.f / deg) * g_aggs[v])
                 : bo_;
        int g = f64 ? (int)((const long long*)batch)[v]
                    : ((const int*)batch)[v];
        atomicMax(&smax[g], enc_f(no));
    }
    __syncthreads();
    if (t < GMAX && smax[t] != ENC_NEG_INF)
        atomicMax(&g_outmax[t], smax[t]);
    __syncthreads();
    if (t == 0) {
        __threadfence();
        s_done = (atomicAdd(&g_done, 1u) == gridDim.x - 1u);
    }
    __syncthreads();
    if (s_done && t < GMAX && t < out_n) {
        unsigned vmax = atomicAdd(&g_outmax[t], 0u);  // coherent L2 read
        out[t] = dec_f(vmax);
    }
}

extern "C" void kernel_launch(void* const* d_in, const int* in_sizes, int n_in,
                              void* d_out, int out_size) {
    const float* x     = (const float*)d_in[0];
    const void*  ei    = d_in[1];
    const void*  batch = d_in[2];
    const float* Wv  = (const float*)d_in[3];
    const float* bv  = (const float*)d_in[4];
    const float* We1 = (const float*)d_in[5];
    const float* be1 = (const float*)d_in[6];
    const float* Wx  = (const float*)d_in[7];
    const float* bx  = (const float*)d_in[8];
    const float* We2 = (const float*)d_in[9];
    const float* be2 = (const float*)d_in[10];
    const float* Wo  = (const float*)d_in[11];
    const float* bo  = (const float*)d_in[12];
    float* out = (float*)d_out;

    int n = in_sizes[0] / 11;   // 100000
    int E = in_sizes[1] / 2;    // 1600000
    if (n > NMAX) n = NMAX;
    if (E > 2 * EMAXH) E = 2 * EMAXH;

    const int TPB = 256;
    int nb_n = (n + TPB - 1) / TPB;
    int nb_e = ((E + 1) / 2 + TPB - 1) / TPB;

    k_fold<<<1, 256>>>(Wv, bv, We1, be1, Wx, bx, We2, be2, Wo, bo,
                       (const unsigned*)ei);
    k_dots<<<nb_n, TPB>>>(x, n);
    k_edge1<<<nb_e, TPB>>>(ei, E);
    k_edge2<<<nb_e, TPB>>>(E);
    k_final<<<nb_n, TPB>>>(batch, out, n, out_size);
}

// round 13
// speedup vs baseline: 1.0590x; 1.0013x over previous
#include <cuda_runtime.h>

// Fixed problem shape (GNNReachabilityNet): N=100000 nodes, E=1600000 edges, G=64 graphs.
#define NMAX  100352
#define GMAX  64
#define EMAXH 800000   // max edge pairs (E/2)

struct Params {
    float p1[11], q1[11], p2[11], q2[11];
    float ps, qs, s0, b2, bo;
};

__device__ Params   gP;
__device__ float    g_alpha[NMAX];   // alpha = x.p2
__device__ float4   g_node[NMAX];    // (beta+gamma+ps, beta+s0, sum_alpha, deg)
__device__ float    g_delta[NMAX];   // delta = x.q1
__device__ float    g_aggs[NMAX];    // sum of w[src] over incoming
__device__ int4     g_eidx[EMAXH];   // packed (s0,d0,s1,d1) per edge pair
__device__ unsigned g_outmax[GMAX];  // order-encoded float max
__device__ unsigned g_done = 0;
__device__ int      g_flag;          // 1 = int64 indices, 0 = int32

__device__ __forceinline__ unsigned enc_f(float f) {
    unsigned u = __float_as_uint(f);
    return (u & 0x80000000u) ? ~u : (u | 0x80000000u);
}
__device__ __forceinline__ float dec_f(unsigned e) {
    return (e & 0x80000000u) ? __uint_as_float(e ^ 0x80000000u) : __uint_as_float(~e);
}
#define ENC_NEG_INF 0x007FFFFFu

// ---------------------------------------------------------------------------
// K1: weight fold, coalesced loops (proven R3/R9 pattern), fp32.
// Also: dtype detect, init g_outmax / g_done.
// ---------------------------------------------------------------------------
__global__ void k_fold(const float* __restrict__ Wv,  const float* __restrict__ bv,
                       const float* __restrict__ We1, const float* __restrict__ be1,
                       const float* __restrict__ Wx,  const float* __restrict__ bx,
                       const float* __restrict__ We2, const float* __restrict__ be2,
                       const float* __restrict__ Wo,  const float* __restrict__ bo,
                       const unsigned* __restrict__ ei_words) {
    __shared__ float M1[11 * 128], M2[11 * 128];
    __shared__ float A1[11 * 64],  A2[11 * 64];
    __shared__ float c1[128], c2[64], wev[64], wfv[64];
    const int t = threadIdx.x;  // 256 threads

    if (t == 0) {
        // int64 little-endian nonneg < 2^31 => odd 32-bit words all zero.
        int nz = 0;
#pragma unroll
        for (int i = 0; i < 64; i++) nz += (ei_words[2 * i + 1] != 0u);
        g_flag = (nz == 0);
        g_done = 0u;
    }
    if (t < GMAX) g_outmax[t] = ENC_NEG_INF;

    // M1 = Wv@Wa + Pc, M2 = Wv@Wb + Pd  (coalesced over m)
    for (int idx = t; idx < 11 * 128; idx += 256) {
        int i = idx / 128, m = idx % 128;
        float a1 = 0.f, a2 = 0.f;
        for (int k = 0; k < 64; k++) {
            float wk = Wv[i * 64 + k];
            a1 += wk * We1[k * 128 + m];
            a2 += wk * We1[(64 + k) * 128 + m];
        }
        if (i == 9)  { a1 += We1[128 * 128 + m]; a2 += We1[130 * 128 + m]; }
        if (i == 10) { a1 += We1[129 * 128 + m]; a2 += We1[131 * 128 + m]; }
        M1[idx] = a1; M2[idx] = a2;
    }
    for (int m = t; m < 128; m += 256) {
        float c = be1[m];
        for (int k = 0; k < 64; k++)
            c += bv[k] * (We1[k * 128 + m] + We1[(64 + k) * 128 + m]);
        c1[m] = c;
    }
    for (int j = t; j < 64; j += 256) {
        float a = 0.f, b = 0.f;
        for (int o = 0; o < 64; o++) {
            a += We2[j * 64 + o]        * Wo[o];
            b += We2[(64 + j) * 64 + o] * Wo[o];
        }
        wev[j] = a; wfv[j] = b;
    }
    __syncthreads();
    // A1 = M1@Wx, A2 = M2@Wx  (coalesced over o)
    for (int idx = t; idx < 11 * 64; idx += 256) {
        int i = idx / 64, o = idx % 64;
        float a1 = 0.f, a2 = 0.f;
        for (int m = 0; m < 128; m++) {
            float wx = Wx[m * 64 + o];
            a1 += M1[i * 128 + m] * wx;
            a2 += M2[i * 128 + m] * wx;
        }
        A1[idx] = a1; A2[idx] = a2;
    }
    for (int o = t; o < 64; o += 256) {
        float c = bx[o];
        for (int m = 0; m < 128; m++) c += c1[m] * Wx[m * 64 + o];
        c2[o] = c;
    }
    __syncthreads();
    if (t < 11) {
        int i = t;
        float a = 0.f, b = 0.f, g = 0.f, d = 0.f;
        for (int o = 0; o < 64; o++) {
            a += A2[i * 64 + o] * wfv[o]; // p2 -> alpha
            b += A2[i * 64 + o] * wev[o]; // q2 -> beta
            g += A1[i * 64 + o] * wfv[o]; // p1 -> gamma
            d += A1[i * 64 + o] * wev[o]; // q1 -> delta
        }
        gP.p2[i] = a; gP.q2[i] = b;
        gP.p1[i] = g; gP.q1[i] = d;
    }
    if (t == 32) {
        float ps = 0.f, qs = 0.f, s0 = 0.f, b2 = 0.f;
        for (int o = 0; o < 64; o++) {
            ps += c2[o] * wfv[o];
            qs += c2[o] * wev[o];
            s0 += bx[o] * wfv[o];
            b2 += be2[o] * Wo[o];
        }
        gP.ps = ps; gP.qs = qs; gP.s0 = s0;
        gP.b2 = b2 + bo[0]; gP.bo = bo[0];
    }
}

// ---------------------------------------------------------------------------
// K2: per-node 11-dim dots (x staged via smem float4); writes the packed
// node record (statics + zeroed accumulators) and zeroes g_aggs.
// ---------------------------------------------------------------------------
__global__ void __launch_bounds__(256) k_dots(const float* __restrict__ x, int n) {
    __shared__ float sx[256 * 11];
    __shared__ float sp1[11], sq1[11], sp2[11], sq2[11];
    __shared__ float s_ps, s_s0;
    int t = threadIdx.x;
    if (t < 11) {
        sp1[t] = gP.p1[t]; sq1[t] = gP.q1[t];
        sp2[t] = gP.p2[t]; sq2[t] = gP.q2[t];
    }
    if (t == 11) { s_ps = gP.ps; s_s0 = gP.s0; }
    int base = blockIdx.x * 2816;
    int lim = n * 11 - base;
    if (lim >= 2816) {
        const float4* xv = (const float4*)(x + base);
        float4* s4 = (float4*)sx;
        s4[t]       = xv[t];
        s4[t + 256] = xv[t + 256];
        if (t + 512 < 704) s4[t + 512] = xv[t + 512];
    } else {
        for (int j = t; j < 2816; j += 256)
            sx[j] = (j < lim) ? x[base + j] : 0.f;
    }
    __syncthreads();
    int v = blockIdx.x * 256 + t;
    if (v < n) {
        float a = 0.f, b = 0.f, g = 0.f, d = 0.f;
#pragma unroll
        for (int i = 0; i < 11; i++) {
            float xv = sx[t * 11 + i];
            a += xv * sp2[i]; b += xv * sq2[i];
            g += xv * sp1[i]; d += xv * sq1[i];
        }
        g_alpha[v] = a;
        g_node[v]  = make_float4(b + g + s_ps, b + s_s0, 0.f, 0.f);
        g_delta[v] = d;
        g_aggs[v]  = 0.f;
    }
}

// ---------------------------------------------------------------------------
// K3: edge pass 1 — grid-stride, 2 edges/iter: wide index loads, write
// packed int32 pairs for pass 2, gather alpha (4B), float2 RED into .zw.
// Grid sized to whole waves (host) to kill wave-quantization tail.
// ---------------------------------------------------------------------------
__global__ void __launch_bounds__(256) k_edge1(const void* __restrict__ ei,
                                               int E, int npair) {
    const bool f64 = (g_flag != 0);
    const int stride = gridDim.x * 256;
    for (int i = blockIdx.x * 256 + threadIdx.x; i < npair; i += stride) {
        int e0 = 2 * i;
        int s0, s1, d0, d1;
        bool two = (e0 + 1 < E);
        if (f64) {
            const long long* p = (const long long*)ei;
            if (two) {
                longlong2 sv = *(const longlong2*)(p + e0);
                s0 = (int)sv.x; s1 = (int)sv.y;
                if ((E & 1) == 0) {
                    longlong2 dv = *(const longlong2*)(p + E + e0);
                    d0 = (int)dv.x; d1 = (int)dv.y;
                } else {
                    d0 = (int)p[E + e0]; d1 = (int)p[E + e0 + 1];
                }
            } else {
                s0 = (int)p[e0]; d0 = (int)p[E + e0]; s1 = s0; d1 = -1;
            }
        } else {
            const int* p = (const int*)ei;
            if (two) {
                int2 sv = *(const int2*)(p + e0);
                s0 = sv.x; s1 = sv.y;
                if ((E & 1) == 0) {
                    int2 dv = *(const int2*)(p + E + e0);
                    d0 = dv.x; d1 = dv.y;
                } else {
                    d0 = p[E + e0]; d1 = p[E + e0 + 1];
                }
            } else {
                s0 = p[e0]; d0 = p[E + e0]; s1 = s0; d1 = -1;
            }
        }
        g_eidx[i] = make_int4(s0, d0, s1, d1);

        float2* acc0 = (float2*)((char*)&g_node[d0] + 8);   // .zw half
        float a0 = __ldg(&g_alpha[s0]);
        if (d1 >= 0) {
            float a1 = __ldg(&g_alpha[s1]);
            if (d0 == d1) {
                atomicAdd(acc0, make_float2(a0 + a1, 2.f));
            } else {
                float2* acc1 = (float2*)((char*)&g_node[d1] + 8);
                atomicAdd(acc0, make_float2(a0, 1.f));
                atomicAdd(acc1, make_float2(a1, 1.f));
            }
        } else {
            atomicAdd(acc0, make_float2(a0, 1.f));
        }
    }
}

// ---------------------------------------------------------------------------
// K4: edge pass 2 — grid-stride, 2 edges/iter: ONE 16B gather of the src
// node record, inline w = deg>0 ? x + z/deg : y, scalar RED on dst.
// ---------------------------------------------------------------------------
__global__ void __launch_bounds__(256) k_edge2(int E, int npair) {
    const int stride = gridDim.x * 256;
    for (int i = blockIdx.x * 256 + threadIdx.x; i < npair; i += stride) {
        int4 p = g_eidx[i];
        float4 n0 = __ldg(&g_node[p.x]);
        float w0 = (n0.w > 0.f) ? (n0.x + __fdividef(n0.z, n0.w)) : n0.y;
        if (p.w >= 0) {
            float4 n1 = __ldg(&g_node[p.z]);
            float w1 = (n1.w > 0.f) ? (n1.x + __fdividef(n1.z, n1.w)) : n1.y;
            if (p.y == p.w) {
                atomicAdd(&g_aggs[p.y], w0 + w1);
            } else {
                atomicAdd(&g_aggs[p.y], w0);
                atomicAdd(&g_aggs[p.w], w1);
            }
        } else {
            atomicAdd(&g_aggs[p.y], w0);
        }
    }
}

// ---------------------------------------------------------------------------
// K5: node_out + segment max + last-block writeout. Coalesced float4 load
// of the node record (deg in .w).
// ---------------------------------------------------------------------------
__global__ void __launch_bounds__(256) k_final(const void* __restrict__ batch,
                                               float* out, int n, int out_n) {
    __shared__ unsigned smax[GMAX];
    __shared__ int s_done;
    int t = threadIdx.x;
    if (t < GMAX) smax[t] = ENC_NEG_INF;
    __syncthreads();

    const bool f64 = (g_flag != 0);
    float qb = gP.qs + gP.b2, bo_ = gP.bo;
    int v = blockIdx.x * 256 + t;
    if (v < n) {
        float4 nv = g_node[v];                 // coalesced LDG.128
        float no = (nv.w > 0.f)
                 ? (g_delta[v] + qb + (1.f / nv.w) * g_aggs[v])
                 : bo_;
        int g = f64 ? (int)((const long long*)batch)[v]
                    : ((const int*)batch)[v];
        atomicMax(&smax[g], enc_f(no));
    }
    __syncthreads();
    if (t < GMAX && smax[t] != ENC_NEG_INF)
        atomicMax(&g_outmax[t], smax[t]);
    __syncthreads();
    if (t == 0) {
        __threadfence();
        s_done = (atomicAdd(&g_done, 1u) == gridDim.x - 1u);
    }
    __syncthreads();
    if (s_done && t < GMAX && t < out_n) {
        unsigned vmax = atomicAdd(&g_outmax[t], 0u);  // coherent L2 read
        out[t] = dec_f(vmax);
    }
}

extern "C" void kernel_launch(void* const* d_in, const int* in_sizes, int n_in,
                              void* d_out, int out_size) {
    const float* x     = (const float*)d_in[0];
    const void*  ei    = d_in[1];
    const void*  batch = d_in[2];
    const float* Wv  = (const float*)d_in[3];
    const float* bv  = (const float*)d_in[4];
    const float* We1 = (const float*)d_in[5];
    const float* be1 = (const float*)d_in[6];
    const float* Wx  = (const float*)d_in[7];
    const float* bx  = (const float*)d_in[8];
    const float* We2 = (const float*)d_in[9];
    const float* be2 = (const float*)d_in[10];
    const float* Wo  = (const float*)d_in[11];
    const float* bo  = (const float*)d_in[12];
    float* out = (float*)d_out;

    int n = in_sizes[0] / 11;   // 100000
    int E = in_sizes[1] / 2;    // 1600000
    if (n > NMAX) n = NMAX;
    if (E > 2 * EMAXH) E = 2 * EMAXH;
    int npair = (E + 1) / 2;

    const int TPB = 256;
    int nb_n = (n + TPB - 1) / TPB;
    int nb_needed = (npair + TPB - 1) / TPB;

    // Edge grids sized to whole waves (kill wave-quantization tail).
    int sms = 148;
    cudaDeviceGetAttribute(&sms, cudaDevAttrMultiProcessorCount, 0);
    int bpm1 = 0, bpm2 = 0;
    cudaOccupancyMaxActiveBlocksPerMultiprocessor(&bpm1, k_edge1, TPB, 0);
    cudaOccupancyMaxActiveBlocksPerMultiprocessor(&bpm2, k_edge2, TPB, 0);
    if (bpm1 < 1) bpm1 = 1;
    if (bpm2 < 1) bpm2 = 1;
    int nb_e1 = sms * bpm1; if (nb_e1 > nb_needed) nb_e1 = nb_needed;
    int nb_e2 = sms * bpm2; if (nb_e2 > nb_needed) nb_e2 = nb_needed;

    k_fold<<<1, 256>>>(Wv, bv, We1, be1, Wx, bx, We2, be2, Wo, bo,
                       (const unsigned*)ei);
    k_dots<<<nb_n, TPB>>>(x, n);
    k_edge1<<<nb_e1, TPB>>>(ei, E, npair);
    k_edge2<<<nb_e2, TPB>>>(E, npair);
    k_final<<<nb_n, TPB>>>(batch, out, n, out_size);
}